// round 13
// baseline (speedup 1.0000x reference)
#include <cuda_runtime.h>
#include <math.h>

#define D_MODEL  1024
#define D_FF     4096
#define N_EXPERTS 8
#define T_TOKENS 8192
#define TOPK     2
#define NPAIRS   (T_TOKENS * TOPK)          // 16384

#define BM  128                              // CTA tile M
#define BN  128                              // CTA tile N
#define TKK 16
#define SK  (TKK + 4)                        // smem row stride (words) -> conflict-free frag reads
#define STAGES 2
#define ROWS_CAP  (NPAIRS + N_EXPERTS * BM) // 17408
#define MAX_TILES (ROWS_CAP / BM)           // 136

// ---------------- static device scratch (allocation-free) ----------------
__device__ float g_H[(size_t)ROWS_CAP * D_FF];   // gelu(x@w1^T); pad rows stay 0
__device__ int   g_sorted_token[ROWS_CAP];
__device__ float g_sorted_gate[ROWS_CAP];
__device__ int   g_off[N_EXPERTS + 1];
__device__ int   g_count[N_EXPERTS];
__device__ int   g_tile_expert[MAX_TILES];
__device__ int   g_pair_expert[NPAIRS];
__device__ float g_pair_gate[NPAIRS];
__device__ int   g_pair_rank[NPAIRS];

// ---------------- helpers ----------------
__device__ __forceinline__ unsigned f2tf(float f) {
    unsigned u;
    asm("cvt.rna.tf32.f32 %0, %1;" : "=r"(u) : "f"(f));
    return u;
}

__device__ __forceinline__ void mma_tf32(float* c, const unsigned* a, const unsigned* b) {
    asm volatile(
        "mma.sync.aligned.m16n8k8.row.col.f32.tf32.tf32.f32 "
        "{%0,%1,%2,%3}, {%4,%5,%6,%7}, {%8,%9}, {%0,%1,%2,%3};"
        : "+f"(c[0]), "+f"(c[1]), "+f"(c[2]), "+f"(c[3])
        : "r"(a[0]), "r"(a[1]), "r"(a[2]), "r"(a[3]), "r"(b[0]), "r"(b[1]));
}

__device__ __forceinline__ void cp16(unsigned dst, const void* src, int src_bytes) {
    asm volatile("cp.async.cg.shared.global [%0], [%1], 16, %2;"
                 :: "r"(dst), "l"(src), "r"(src_bytes));
}
__device__ __forceinline__ void cp_commit() {
    asm volatile("cp.async.commit_group;");
}
template <int N>
__device__ __forceinline__ void cp_wait() {
    asm volatile("cp.async.wait_group %0;" :: "n"(N));
}

// ---------------- init ----------------
__global__ void k_init(float* __restrict__ out) {
    int stride = gridDim.x * blockDim.x;
    int i0 = blockIdx.x * blockDim.x + threadIdx.x;
    const int n = T_TOKENS * D_MODEL;
    for (int i = i0; i < n; i += stride) out[i] = 0.0f;
    for (int i = i0; i < ROWS_CAP; i += stride) g_sorted_token[i] = -1;
    if (i0 < N_EXPERTS) g_count[i0] = 0;
}

// ---------------- router: one warp per token ----------------
__global__ void k_router(const float* __restrict__ x,
                         const float* __restrict__ rw,
                         const float* __restrict__ rb) {
    int warp = (blockIdx.x * blockDim.x + threadIdx.x) >> 5;
    int lane = threadIdx.x & 31;
    if (warp >= T_TOKENS) return;
    const float* xt = x + (size_t)warp * D_MODEL;

    float lg[N_EXPERTS];
#pragma unroll
    for (int e = 0; e < N_EXPERTS; e++) {
        const float* we = rw + e * D_MODEL;
        float s = 0.0f;
        for (int d = lane; d < D_MODEL; d += 32) s = fmaf(xt[d], we[d], s);
#pragma unroll
        for (int o = 16; o > 0; o >>= 1) s += __shfl_down_sync(0xffffffffu, s, o);
        lg[e] = s;
    }
    if (lane == 0) {
        float m = -1e30f;
#pragma unroll
        for (int e = 0; e < N_EXPERTS; e++) { lg[e] += rb[e]; m = fmaxf(m, lg[e]); }
        float p[N_EXPERTS];
#pragma unroll
        for (int e = 0; e < N_EXPERTS; e++) p[e] = expf(lg[e] - m);
        int i1 = 0;
#pragma unroll
        for (int e = 1; e < N_EXPERTS; e++) if (p[e] > p[i1]) i1 = e;
        int i2 = (i1 == 0) ? 1 : 0;
#pragma unroll
        for (int e = 0; e < N_EXPERTS; e++) if (e != i1 && p[e] > p[i2]) i2 = e;
        float s2 = p[i1] + p[i2];
        g_pair_expert[warp * 2 + 0] = i1;
        g_pair_expert[warp * 2 + 1] = i2;
        g_pair_gate[warp * 2 + 0] = p[i1] / s2;
        g_pair_gate[warp * 2 + 1] = p[i2] / s2;
        g_pair_rank[warp * 2 + 0] = atomicAdd(&g_count[i1], 1);
        g_pair_rank[warp * 2 + 1] = atomicAdd(&g_count[i2], 1);
    }
}

// ---------------- offsets + tile->expert map ----------------
__global__ void k_setup() {
    int off = 0;
    for (int e = 0; e < N_EXPERTS; e++) {
        g_off[e] = off;
        off += (g_count[e] + BM - 1) / BM * BM;
    }
    g_off[N_EXPERTS] = off;
    int nt = off / BM;
    for (int i = 0; i < MAX_TILES; i++) {
        int te = -1;
        if (i < nt) {
            int r = i * BM;
            for (int e = 0; e < N_EXPERTS; e++)
                if (r >= g_off[e] && r < g_off[e + 1]) { te = e; break; }
        }
        g_tile_expert[i] = te;
    }
}

// ---------------- scatter ----------------
__global__ void k_scatter() {
    int i = blockIdx.x * blockDim.x + threadIdx.x;
    if (i >= NPAIRS) return;
    int e = g_pair_expert[i];
    int r = g_off[e] + g_pair_rank[i];
    g_sorted_token[r] = i >> 1;
    g_sorted_gate[r]  = g_pair_gate[i];
}

// ======================================================================
// pass 1: H = gelu(X_e @ w1[e]^T + b1[e])
// CTA tile 128x128x16, warp tile 64x32 (2Mx4N warps), tf32 mma.sync,
// cp.async double-buffered.
// ======================================================================
__global__ void __launch_bounds__(256) k_ffn1(const float* __restrict__ x,
                                              const float* __restrict__ w1,
                                              const float* __restrict__ b1) {
    int e = g_tile_expert[blockIdx.x];
    if (e < 0) return;
    int r0 = blockIdx.x * BM;
    int f0 = blockIdx.y * BN;

    __shared__ float As[STAGES][BM][SK];
    __shared__ float Bs[STAGES][BN][SK];
    __shared__ int tok[BM];

    int tid = threadIdx.x;
    if (tid < BM) tok[tid] = g_sorted_token[r0 + tid];
    __syncthreads();
    if (tok[0] < 0) return;

    int lane = tid & 31, wid = tid >> 5;
    int wm = (wid & 1) * 64;          // warp M offset (0 or 64)
    int wn = (wid >> 1) * 32;         // warp N offset (0..96)
    int g = lane >> 2, q = lane & 3;

    // per-thread cp.async slots (k-invariant): 512 float4 per matrix / 256 thr = 2 each
    int row0 = tid >> 2, cA = tid & 3;
    int row1 = row0 + 64;
    int t0 = tok[row0], t1 = tok[row1];
    const float* srcA0 = x + (t0 >= 0 ? (size_t)t0 * D_MODEL : 0) + cA * 4;
    const float* srcA1 = x + (t1 >= 0 ? (size_t)t1 * D_MODEL : 0) + cA * 4;
    int szA0 = t0 >= 0 ? 16 : 0, szA1 = t1 >= 0 ? 16 : 0;
    const float* wb = w1 + ((size_t)e * D_FF + f0) * D_MODEL;
    const float* srcB0 = wb + (size_t)row0 * D_MODEL + cA * 4;
    const float* srcB1 = wb + (size_t)row1 * D_MODEL + cA * 4;

    unsigned dA0[STAGES], dA1[STAGES], dB0[STAGES], dB1[STAGES];
#pragma unroll
    for (int s = 0; s < STAGES; s++) {
        dA0[s] = (unsigned)__cvta_generic_to_shared(&As[s][row0][cA * 4]);
        dA1[s] = (unsigned)__cvta_generic_to_shared(&As[s][row1][cA * 4]);
        dB0[s] = (unsigned)__cvta_generic_to_shared(&Bs[s][row0][cA * 4]);
        dB1[s] = (unsigned)__cvta_generic_to_shared(&Bs[s][row1][cA * 4]);
    }

    float acc[4][4][4] = {};
    const int NK = D_MODEL / TKK;

    cp16(dA0[0], srcA0, szA0);
    cp16(dA1[0], srcA1, szA1);
    cp16(dB0[0], srcB0, 16);
    cp16(dB1[0], srcB1, 16);
    cp_commit();
    srcA0 += TKK; srcA1 += TKK; srcB0 += TKK; srcB1 += TKK;

    for (int k0 = 0; k0 < NK; k0++) {
        int s = k0 & 1;
        if (k0 + 1 < NK) {
            int sn = s ^ 1;
            cp16(dA0[sn], srcA0, szA0);
            cp16(dA1[sn], srcA1, szA1);
            cp16(dB0[sn], srcB0, 16);
            cp16(dB1[sn], srcB1, 16);
            cp_commit();
            srcA0 += TKK; srcA1 += TKK; srcB0 += TKK; srcB1 += TKK;
            cp_wait<1>();
        } else {
            cp_wait<0>();
        }
        __syncthreads();
#pragma unroll
        for (int k8 = 0; k8 < TKK; k8 += 8) {
            unsigned a[4][4], b[4][2];
#pragma unroll
            for (int mi = 0; mi < 4; mi++) {
                int rbase = wm + mi * 16 + g;
                a[mi][0] = f2tf(As[s][rbase][k8 + q]);
                a[mi][1] = f2tf(As[s][rbase + 8][k8 + q]);
                a[mi][2] = f2tf(As[s][rbase][k8 + q + 4]);
                a[mi][3] = f2tf(As[s][rbase + 8][k8 + q + 4]);
            }
#pragma unroll
            for (int ni = 0; ni < 4; ni++) {
                int cbase = wn + ni * 8 + g;
                b[ni][0] = f2tf(Bs[s][cbase][k8 + q]);
                b[ni][1] = f2tf(Bs[s][cbase][k8 + q + 4]);
            }
#pragma unroll
            for (int mi = 0; mi < 4; mi++)
#pragma unroll
                for (int ni = 0; ni < 4; ni++)
                    mma_tf32(acc[mi][ni], a[mi], b[ni]);
        }
        __syncthreads();
    }

    // epilogue: bias + exact gelu
#pragma unroll
    for (int mi = 0; mi < 4; mi++) {
#pragma unroll
        for (int half = 0; half < 2; half++) {
            int row = wm + mi * 16 + g + half * 8;
            int t = tok[row];
            if (t < 0) continue;
#pragma unroll
            for (int ni = 0; ni < 4; ni++) {
                int col = f0 + wn + ni * 8 + q * 2;
                float v0 = acc[mi][ni][half * 2 + 0] + b1[e * D_FF + col];
                float v1 = acc[mi][ni][half * 2 + 1] + b1[e * D_FF + col + 1];
                v0 = 0.5f * v0 * (1.0f + erff(v0 * 0.70710678118654752f));
                v1 = 0.5f * v1 * (1.0f + erff(v1 * 0.70710678118654752f));
                *(float2*)&g_H[(size_t)(r0 + row) * D_FF + col] = make_float2(v0, v1);
            }
        }
    }
}

// ======================================================================
// pass 2: out += gate * (H @ w2[e]^T + b2[e])
// grid (n-tile, m-tile) so concurrent CTAs share H rows in L2.
// ======================================================================
__global__ void __launch_bounds__(256) k_ffn2(const float* __restrict__ w2,
                                              const float* __restrict__ b2,
                                              float* __restrict__ out) {
    int e = g_tile_expert[blockIdx.y];
    if (e < 0) return;
    int r0 = blockIdx.y * BM;
    int c0 = blockIdx.x * BN;

    __shared__ float As[STAGES][BM][SK];
    __shared__ float Bs[STAGES][BN][SK];
    __shared__ int tok[BM];
    __shared__ float gate[BM];

    int tid = threadIdx.x;
    if (tid < BM) {
        tok[tid]  = g_sorted_token[r0 + tid];
        gate[tid] = g_sorted_gate[r0 + tid];
    }
    __syncthreads();
    if (tok[0] < 0) return;

    int lane = tid & 31, wid = tid >> 5;
    int wm = (wid & 1) * 64;
    int wn = (wid >> 1) * 32;
    int g = lane >> 2, q = lane & 3;

    int row0 = tid >> 2, cA = tid & 3;
    int row1 = row0 + 64;
    const float* ha = g_H + (size_t)r0 * D_FF;
    const float* srcA0 = ha + (size_t)row0 * D_FF + cA * 4;   // pad rows read zeros
    const float* srcA1 = ha + (size_t)row1 * D_FF + cA * 4;
    const float* wb = w2 + ((size_t)e * D_MODEL + c0) * D_FF;
    const float* srcB0 = wb + (size_t)row0 * D_FF + cA * 4;
    const float* srcB1 = wb + (size_t)row1 * D_FF + cA * 4;

    unsigned dA0[STAGES], dA1[STAGES], dB0[STAGES], dB1[STAGES];
#pragma unroll
    for (int s = 0; s < STAGES; s++) {
        dA0[s] = (unsigned)__cvta_generic_to_shared(&As[s][row0][cA * 4]);
        dA1[s] = (unsigned)__cvta_generic_to_shared(&As[s][row1][cA * 4]);
        dB0[s] = (unsigned)__cvta_generic_to_shared(&Bs[s][row0][cA * 4]);
        dB1[s] = (unsigned)__cvta_generic_to_shared(&Bs[s][row1][cA * 4]);
    }

    float acc[4][4][4] = {};
    const int NK = D_FF / TKK;

    cp16(dA0[0], srcA0, 16);
    cp16(dA1[0], srcA1, 16);
    cp16(dB0[0], srcB0, 16);
    cp16(dB1[0], srcB1, 16);
    cp_commit();
    srcA0 += TKK; srcA1 += TKK; srcB0 += TKK; srcB1 += TKK;

    for (int k0 = 0; k0 < NK; k0++) {
        int s = k0 & 1;
        if (k0 + 1 < NK) {
            int sn = s ^ 1;
            cp16(dA0[sn], srcA0, 16);
            cp16(dA1[sn], srcA1, 16);
            cp16(dB0[sn], srcB0, 16);
            cp16(dB1[sn], srcB1, 16);
            cp_commit();
            srcA0 += TKK; srcA1 += TKK; srcB0 += TKK; srcB1 += TKK;
            cp_wait<1>();
        } else {
            cp_wait<0>();
        }
        __syncthreads();
#pragma unroll
        for (int k8 = 0; k8 < TKK; k8 += 8) {
            unsigned a[4][4], b[4][2];
#pragma unroll
            for (int mi = 0; mi < 4; mi++) {
                int rbase = wm + mi * 16 + g;
                a[mi][0] = f2tf(As[s][rbase][k8 + q]);
                a[mi][1] = f2tf(As[s][rbase + 8][k8 + q]);
                a[mi][2] = f2tf(As[s][rbase][k8 + q + 4]);
                a[mi][3] = f2tf(As[s][rbase + 8][k8 + q + 4]);
            }
#pragma unroll
            for (int ni = 0; ni < 4; ni++) {
                int cbase = wn + ni * 8 + g;
                b[ni][0] = f2tf(Bs[s][cbase][k8 + q]);
                b[ni][1] = f2tf(Bs[s][cbase][k8 + q + 4]);
            }
#pragma unroll
            for (int mi = 0; mi < 4; mi++)
#pragma unroll
                for (int ni = 0; ni < 4; ni++)
                    mma_tf32(acc[mi][ni], a[mi], b[ni]);
        }
        __syncthreads();
    }

    // epilogue: gate * (acc + bias), 2 commutative atomicAdds per output elem
#pragma unroll
    for (int mi = 0; mi < 4; mi++) {
#pragma unroll
        for (int half = 0; half < 2; half++) {
            int row = wm + mi * 16 + g + half * 8;
            int t = tok[row];
            if (t < 0) continue;
            float gw = gate[row];
#pragma unroll
            for (int ni = 0; ni < 4; ni++) {
                int col = c0 + wn + ni * 8 + q * 2;
                float v0 = gw * (acc[mi][ni][half * 2 + 0] + b2[e * D_MODEL + col]);
                float v1 = gw * (acc[mi][ni][half * 2 + 1] + b2[e * D_MODEL + col + 1]);
                atomicAdd(&out[(size_t)t * D_MODEL + col], v0);
                atomicAdd(&out[(size_t)t * D_MODEL + col + 1], v1);
            }
        }
    }
}

// ---------------- launch ----------------
extern "C" void kernel_launch(void* const* d_in, const int* in_sizes, int n_in,
                              void* d_out, int out_size) {
    (void)in_sizes; (void)n_in; (void)out_size;
    const float* x  = (const float*)d_in[0];
    const float* rw = (const float*)d_in[1];
    const float* rb = (const float*)d_in[2];
    const float* w1 = (const float*)d_in[3];
    const float* b1 = (const float*)d_in[4];
    const float* w2 = (const float*)d_in[5];
    const float* b2 = (const float*)d_in[6];
    float* out = (float*)d_out;

    k_init<<<1024, 256>>>(out);
    k_router<<<T_TOKENS / 8, 256>>>(x, rw, rb);
    k_setup<<<1, 1>>>();
    k_scatter<<<(NPAIRS + 255) / 256, 256>>>();
    k_ffn1<<<dim3(MAX_TILES, D_FF / BN), 256>>>(x, w1, b1);
    k_ffn2<<<dim3(D_MODEL / BN, MAX_TILES), 256>>>(w2, b2, out);
}

// round 15
// speedup vs baseline: 1.5906x; 1.5906x over previous
#include <cuda_runtime.h>
#include <cuda_fp16.h>
#include <math.h>
#include <stdint.h>

#define D_MODEL  1024
#define D_FF     4096
#define N_EXPERTS 8
#define T_TOKENS 8192
#define TOPK     2
#define NPAIRS   (T_TOKENS * TOPK)          // 16384

#define BM  128
#define BN  128
#define KCH 32                               // k halfs per chunk (64B rows)
#define SKW 20                               // smem row stride in half2 words (16 data + 4 pad)
#define STAGES 2
#define ROWS_CAP  (NPAIRS + N_EXPERTS * BM) // 17408
#define MAX_TILES (ROWS_CAP / BM)           // 136

// ---------------- static device scratch (allocation-free) ----------------
__device__ __half g_Hh[(size_t)ROWS_CAP * D_FF];     // gelu(x@w1^T) fp16; pad rows stay 0
__device__ __half g_xh[(size_t)ROWS_CAP * D_MODEL];  // gathered tokens fp16; pads 0
__device__ __half g_w1h[(size_t)N_EXPERTS * D_FF * D_MODEL];
__device__ __half g_w2h[(size_t)N_EXPERTS * D_MODEL * D_FF];
__device__ int   g_sorted_token[ROWS_CAP];
__device__ float g_sorted_gate[ROWS_CAP];
__device__ int   g_off[N_EXPERTS + 1];
__device__ int   g_count[N_EXPERTS];
__device__ int   g_tile_expert[MAX_TILES];
__device__ int   g_pair_expert[NPAIRS];
__device__ float g_pair_gate[NPAIRS];
__device__ int   g_pair_rank[NPAIRS];

// ---------------- helpers ----------------
__device__ __forceinline__ void mma_f16(float* c, const unsigned* a, const unsigned* b) {
    asm volatile(
        "mma.sync.aligned.m16n8k16.row.col.f32.f16.f16.f32 "
        "{%0,%1,%2,%3}, {%4,%5,%6,%7}, {%8,%9}, {%0,%1,%2,%3};"
        : "+f"(c[0]), "+f"(c[1]), "+f"(c[2]), "+f"(c[3])
        : "r"(a[0]), "r"(a[1]), "r"(a[2]), "r"(a[3]), "r"(b[0]), "r"(b[1]));
}
__device__ __forceinline__ void cp16(unsigned dst, const void* src) {
    asm volatile("cp.async.cg.shared.global [%0], [%1], 16;" :: "r"(dst), "l"(src));
}
__device__ __forceinline__ void cp_commit() { asm volatile("cp.async.commit_group;"); }
template <int N> __device__ __forceinline__ void cp_wait() {
    asm volatile("cp.async.wait_group %0;" :: "n"(N));
}

// ---------------- init ----------------
__global__ void k_init(float* __restrict__ out) {
    int stride = gridDim.x * blockDim.x;
    int i0 = blockIdx.x * blockDim.x + threadIdx.x;
    for (int i = i0; i < T_TOKENS * D_MODEL; i += stride) out[i] = 0.0f;
    for (int i = i0; i < ROWS_CAP; i += stride) g_sorted_token[i] = -1;
    if (i0 < N_EXPERTS) g_count[i0] = 0;
}

// ---------------- router: one warp per token ----------------
__global__ void k_router(const float* __restrict__ x, const float* __restrict__ rw,
                         const float* __restrict__ rb) {
    int warp = (blockIdx.x * blockDim.x + threadIdx.x) >> 5;
    int lane = threadIdx.x & 31;
    if (warp >= T_TOKENS) return;
    const float* xt = x + (size_t)warp * D_MODEL;
    float lg[N_EXPERTS];
#pragma unroll
    for (int e = 0; e < N_EXPERTS; e++) {
        const float* we = rw + e * D_MODEL;
        float s = 0.0f;
        for (int d = lane; d < D_MODEL; d += 32) s = fmaf(xt[d], we[d], s);
#pragma unroll
        for (int o = 16; o > 0; o >>= 1) s += __shfl_down_sync(0xffffffffu, s, o);
        lg[e] = s;
    }
    if (lane == 0) {
        float m = -1e30f;
#pragma unroll
        for (int e = 0; e < N_EXPERTS; e++) { lg[e] += rb[e]; m = fmaxf(m, lg[e]); }
        float p[N_EXPERTS];
#pragma unroll
        for (int e = 0; e < N_EXPERTS; e++) p[e] = expf(lg[e] - m);
        int i1 = 0;
#pragma unroll
        for (int e = 1; e < N_EXPERTS; e++) if (p[e] > p[i1]) i1 = e;
        int i2 = (i1 == 0) ? 1 : 0;
#pragma unroll
        for (int e = 0; e < N_EXPERTS; e++) if (e != i1 && p[e] > p[i2]) i2 = e;
        float s2 = p[i1] + p[i2];
        g_pair_expert[warp * 2 + 0] = i1;
        g_pair_expert[warp * 2 + 1] = i2;
        g_pair_gate[warp * 2 + 0] = p[i1] / s2;
        g_pair_gate[warp * 2 + 1] = p[i2] / s2;
        g_pair_rank[warp * 2 + 0] = atomicAdd(&g_count[i1], 1);
        g_pair_rank[warp * 2 + 1] = atomicAdd(&g_count[i2], 1);
    }
}

// ---------------- offsets + tile->expert map ----------------
__global__ void k_setup() {
    int off = 0;
    for (int e = 0; e < N_EXPERTS; e++) {
        g_off[e] = off;
        off += (g_count[e] + BM - 1) / BM * BM;
    }
    g_off[N_EXPERTS] = off;
    int nt = off / BM;
    for (int i = 0; i < MAX_TILES; i++) {
        int te = -1;
        if (i < nt) {
            int r = i * BM;
            for (int e = 0; e < N_EXPERTS; e++)
                if (r >= g_off[e] && r < g_off[e + 1]) { te = e; break; }
        }
        g_tile_expert[i] = te;
    }
}

// ---------------- scatter ----------------
__global__ void k_scatter() {
    int i = blockIdx.x * blockDim.x + threadIdx.x;
    if (i >= NPAIRS) return;
    int e = g_pair_expert[i];
    int r = g_off[e] + g_pair_rank[i];
    g_sorted_token[r] = i >> 1;
    g_sorted_gate[r]  = g_pair_gate[i];
}

// ---------------- prepass: weights -> fp16; gather tokens -> fp16 --------
__global__ void k_prepw(const float* __restrict__ w1, const float* __restrict__ w2) {
    size_t n = (size_t)N_EXPERTS * D_FF * D_MODEL / 4;
    size_t stride = (size_t)gridDim.x * blockDim.x;
    for (size_t i = blockIdx.x * blockDim.x + threadIdx.x; i < n; i += stride) {
        float4 a = ((const float4*)w1)[i];
        ((__half2*)g_w1h)[i * 2 + 0] = __floats2half2_rn(a.x, a.y);
        ((__half2*)g_w1h)[i * 2 + 1] = __floats2half2_rn(a.z, a.w);
        float4 b = ((const float4*)w2)[i];
        ((__half2*)g_w2h)[i * 2 + 0] = __floats2half2_rn(b.x, b.y);
        ((__half2*)g_w2h)[i * 2 + 1] = __floats2half2_rn(b.z, b.w);
    }
}

__global__ void k_gather(const float* __restrict__ x) {
    int r = blockIdx.x;
    int t = g_sorted_token[r];
    int d = threadIdx.x * 4;
    float4 v = make_float4(0.f, 0.f, 0.f, 0.f);
    if (t >= 0) v = *(const float4*)&x[(size_t)t * D_MODEL + d];
    __half2* dst = (__half2*)&g_xh[(size_t)r * D_MODEL + d];
    dst[0] = __floats2half2_rn(v.x, v.y);
    dst[1] = __floats2half2_rn(v.z, v.w);
}

// ======================================================================
// fp16 GEMM: CTA 128x128, warps 2Mx4N (warp tile 64x32), m16n8k16,
// cp.async double-buffered, k-chunk 32 halfs (64B rows).
// G1: A=g_xh, B=g_w1h -> gelu -> g_Hh.   !G1: A=g_Hh, B=g_w2h -> out.
// ======================================================================
template<int KD, bool G1>
__global__ void __launch_bounds__(256) k_gemm(const float* __restrict__ bias,
                                              float* __restrict__ outp) {
    int e, r0, c0;
    if (G1) { e = g_tile_expert[blockIdx.x]; r0 = blockIdx.x * BM; c0 = blockIdx.y * BN; }
    else    { e = g_tile_expert[blockIdx.y]; r0 = blockIdx.y * BM; c0 = blockIdx.x * BN; }
    if (e < 0) return;

    __shared__ unsigned As[STAGES][BM][SKW];   // half2 words
    __shared__ unsigned Bs[STAGES][BN][SKW];
    __shared__ int tok[BM];
    __shared__ float gate[BM];

    int tid = threadIdx.x;
    if (tid < BM) {
        tok[tid]  = g_sorted_token[r0 + tid];
        gate[tid] = g_sorted_gate[r0 + tid];
    }
    __syncthreads();
    if (tok[0] < 0) return;

    int lane = tid & 31, wid = tid >> 5;
    int wm = (wid & 1) * 64;
    int wn = (wid >> 1) * 32;
    int g = lane >> 2, q = lane & 3;

    const __half* Ah = (G1 ? g_xh : g_Hh) + (size_t)r0 * KD;
    const __half* Bh = (G1 ? g_w1h : g_w2h) + ((size_t)e * (G1 ? D_FF : D_MODEL) + c0) * KD;

    // loader slots: 128 rows x 4 16B-chunks = 512 per matrix; 2 per thread each
    int row0 = tid >> 2, cA = tid & 3;
    int row1 = row0 + 64;
    const __half* srcA0 = Ah + (size_t)row0 * KD + cA * 8;
    const __half* srcA1 = Ah + (size_t)row1 * KD + cA * 8;
    const __half* srcB0 = Bh + (size_t)row0 * KD + cA * 8;
    const __half* srcB1 = Bh + (size_t)row1 * KD + cA * 8;

    unsigned dA0[STAGES], dA1[STAGES], dB0[STAGES], dB1[STAGES];
#pragma unroll
    for (int s = 0; s < STAGES; s++) {
        dA0[s] = (unsigned)__cvta_generic_to_shared(&As[s][row0][cA * 4]);
        dA1[s] = (unsigned)__cvta_generic_to_shared(&As[s][row1][cA * 4]);
        dB0[s] = (unsigned)__cvta_generic_to_shared(&Bs[s][row0][cA * 4]);
        dB1[s] = (unsigned)__cvta_generic_to_shared(&Bs[s][row1][cA * 4]);
    }

    float acc[4][4][4] = {};
    const int NK = KD / KCH;

    cp16(dA0[0], srcA0); cp16(dA1[0], srcA1);
    cp16(dB0[0], srcB0); cp16(dB1[0], srcB1);
    cp_commit();
    srcA0 += KCH; srcA1 += KCH; srcB0 += KCH; srcB1 += KCH;

    for (int k0 = 0; k0 < NK; k0++) {
        int s = k0 & 1;
        if (k0 + 1 < NK) {
            int sn = s ^ 1;
            cp16(dA0[sn], srcA0); cp16(dA1[sn], srcA1);
            cp16(dB0[sn], srcB0); cp16(dB1[sn], srcB1);
            cp_commit();
            srcA0 += KCH; srcA1 += KCH; srcB0 += KCH; srcB1 += KCH;
            cp_wait<1>();
        } else {
            cp_wait<0>();
        }
        __syncthreads();
#pragma unroll
        for (int st = 0; st < 2; st++) {        // two k16 steps per chunk
            int ko = st * 8;                     // half2-word offset
            unsigned a[4][4], b[4][2];
#pragma unroll
            for (int mi = 0; mi < 4; mi++) {
                int rb = wm + mi * 16 + g;
                a[mi][0] = As[s][rb][q + ko];
                a[mi][1] = As[s][rb + 8][q + ko];
                a[mi][2] = As[s][rb][q + 4 + ko];
                a[mi][3] = As[s][rb + 8][q + 4 + ko];
            }
#pragma unroll
            for (int ni = 0; ni < 4; ni++) {
                int cb = wn + ni * 8 + g;
                b[ni][0] = Bs[s][cb][q + ko];
                b[ni][1] = Bs[s][cb][q + 4 + ko];
            }
#pragma unroll
            for (int mi = 0; mi < 4; mi++)
#pragma unroll
                for (int ni = 0; ni < 4; ni++)
                    mma_f16(acc[mi][ni], a[mi], b[ni]);
        }
        __syncthreads();
    }

    // epilogue
#pragma unroll
    for (int mi = 0; mi < 4; mi++) {
#pragma unroll
        for (int half = 0; half < 2; half++) {
            int row = wm + mi * 16 + g + half * 8;
            int t = tok[row];
            if (t < 0) continue;
            float gw = gate[row];
#pragma unroll
            for (int ni = 0; ni < 4; ni++) {
                int col = c0 + wn + ni * 8 + q * 2;
                if (G1) {
                    float v0 = acc[mi][ni][half * 2 + 0] + bias[e * D_FF + col];
                    float v1 = acc[mi][ni][half * 2 + 1] + bias[e * D_FF + col + 1];
                    v0 = 0.5f * v0 * (1.0f + erff(v0 * 0.70710678118654752f));
                    v1 = 0.5f * v1 * (1.0f + erff(v1 * 0.70710678118654752f));
                    *(__half2*)&g_Hh[(size_t)(r0 + row) * D_FF + col] =
                        __floats2half2_rn(v0, v1);
                } else {
                    float v0 = gw * (acc[mi][ni][half * 2 + 0] + bias[e * D_MODEL + col]);
                    float v1 = gw * (acc[mi][ni][half * 2 + 1] + bias[e * D_MODEL + col + 1]);
                    atomicAdd(&outp[(size_t)t * D_MODEL + col], v0);
                    atomicAdd(&outp[(size_t)t * D_MODEL + col + 1], v1);
                }
            }
        }
    }
}

// ---------------- launch ----------------
extern "C" void kernel_launch(void* const* d_in, const int* in_sizes, int n_in,
                              void* d_out, int out_size) {
    (void)in_sizes; (void)n_in; (void)out_size;
    const float* x  = (const float*)d_in[0];
    const float* rw = (const float*)d_in[1];
    const float* rb = (const float*)d_in[2];
    const float* w1 = (const float*)d_in[3];
    const float* b1 = (const float*)d_in[4];
    const float* w2 = (const float*)d_in[5];
    const float* b2 = (const float*)d_in[6];
    float* out = (float*)d_out;

    k_init<<<1024, 256>>>(out);
    k_prepw<<<2048, 256>>>(w1, w2);
    k_router<<<T_TOKENS / 8, 256>>>(x, rw, rb);
    k_setup<<<1, 1>>>();
    k_scatter<<<(NPAIRS + 255) / 256, 256>>>();
    k_gather<<<ROWS_CAP, 256>>>(x);
    k_gemm<D_MODEL, true><<<dim3(MAX_TILES, D_FF / BN), 256>>>(b1, (float*)0);
    k_gemm<D_FF, false><<<dim3(D_MODEL / BN, MAX_TILES), 256>>>(b2, out);
}

// round 16
// speedup vs baseline: 1.9908x; 1.2516x over previous
#include <cuda_runtime.h>
#include <cuda_fp16.h>
#include <math.h>
#include <stdint.h>

#define D_MODEL  1024
#define D_FF     4096
#define N_EXPERTS 8
#define T_TOKENS 8192
#define TOPK     2
#define NPAIRS   (T_TOKENS * TOPK)          // 16384

#define BM  128
#define BN  128
#define KCH 32                               // k halfs per chunk (64B rows)
#define SKW 20                               // smem row stride in words (16 data + 4 pad)
#define NSTG 3
#define ROWS_CAP  (NPAIRS + N_EXPERTS * BM) // 17408
#define MAX_TILES (ROWS_CAP / BM)           // 136

#define MAT_STG (BM * SKW * 4)               // 10240 B per stage per matrix
#define OFF_A   0
#define OFF_B   (NSTG * MAT_STG)             // 30720
#define OFF_TOK (2 * NSTG * MAT_STG)         // 61440
#define OFF_GATE (OFF_TOK + 512)
#define SMEM_SZ (OFF_GATE + 512)             // 62464

// ---------------- static device scratch (allocation-free) ----------------
__device__ __half g_Hh[(size_t)ROWS_CAP * D_FF];     // gelu(x@w1^T) fp16; pad rows 0
__device__ __half g_xh[(size_t)ROWS_CAP * D_MODEL];  // gathered tokens fp16; pads 0
__device__ __half g_w1h[(size_t)N_EXPERTS * D_FF * D_MODEL];
__device__ __half g_w2h[(size_t)N_EXPERTS * D_MODEL * D_FF];
__device__ int   g_sorted_token[ROWS_CAP];
__device__ float g_sorted_gate[ROWS_CAP];
__device__ int   g_off[N_EXPERTS + 1];
__device__ int   g_count[N_EXPERTS];
__device__ int   g_tile_expert[MAX_TILES];
__device__ int   g_pair_expert[NPAIRS];
__device__ float g_pair_gate[NPAIRS];
__device__ int   g_pair_rank[NPAIRS];

// ---------------- helpers ----------------
__device__ __forceinline__ void mma_f16(float* c, const unsigned* a, const unsigned* b) {
    asm volatile(
        "mma.sync.aligned.m16n8k16.row.col.f32.f16.f16.f32 "
        "{%0,%1,%2,%3}, {%4,%5,%6,%7}, {%8,%9}, {%0,%1,%2,%3};"
        : "+f"(c[0]), "+f"(c[1]), "+f"(c[2]), "+f"(c[3])
        : "r"(a[0]), "r"(a[1]), "r"(a[2]), "r"(a[3]), "r"(b[0]), "r"(b[1]));
}
__device__ __forceinline__ void ldm_x4(unsigned* r, uint32_t addr) {
    asm volatile("ldmatrix.sync.aligned.m8n8.x4.shared.b16 {%0,%1,%2,%3}, [%4];"
                 : "=r"(r[0]), "=r"(r[1]), "=r"(r[2]), "=r"(r[3]) : "r"(addr));
}
__device__ __forceinline__ void cp16(unsigned dst, const void* src) {
    asm volatile("cp.async.cg.shared.global [%0], [%1], 16;" :: "r"(dst), "l"(src));
}
__device__ __forceinline__ void cp_commit() { asm volatile("cp.async.commit_group;"); }
template <int N> __device__ __forceinline__ void cp_wait() {
    asm volatile("cp.async.wait_group %0;" :: "n"(N));
}

// ---------------- init ----------------
__global__ void k_init(float* __restrict__ out) {
    int stride = gridDim.x * blockDim.x;
    int i0 = blockIdx.x * blockDim.x + threadIdx.x;
    for (int i = i0; i < T_TOKENS * D_MODEL; i += stride) out[i] = 0.0f;
    for (int i = i0; i < ROWS_CAP; i += stride) g_sorted_token[i] = -1;
    if (i0 < N_EXPERTS) g_count[i0] = 0;
}

// ---------------- router: one warp per token ----------------
__global__ void k_router(const float* __restrict__ x, const float* __restrict__ rw,
                         const float* __restrict__ rb) {
    int warp = (blockIdx.x * blockDim.x + threadIdx.x) >> 5;
    int lane = threadIdx.x & 31;
    if (warp >= T_TOKENS) return;
    const float* xt = x + (size_t)warp * D_MODEL;
    float lg[N_EXPERTS];
#pragma unroll
    for (int e = 0; e < N_EXPERTS; e++) {
        const float* we = rw + e * D_MODEL;
        float s = 0.0f;
        for (int d = lane; d < D_MODEL; d += 32) s = fmaf(xt[d], we[d], s);
#pragma unroll
        for (int o = 16; o > 0; o >>= 1) s += __shfl_down_sync(0xffffffffu, s, o);
        lg[e] = s;
    }
    if (lane == 0) {
        float m = -1e30f;
#pragma unroll
        for (int e = 0; e < N_EXPERTS; e++) { lg[e] += rb[e]; m = fmaxf(m, lg[e]); }
        float p[N_EXPERTS];
#pragma unroll
        for (int e = 0; e < N_EXPERTS; e++) p[e] = expf(lg[e] - m);
        int i1 = 0;
#pragma unroll
        for (int e = 1; e < N_EXPERTS; e++) if (p[e] > p[i1]) i1 = e;
        int i2 = (i1 == 0) ? 1 : 0;
#pragma unroll
        for (int e = 0; e < N_EXPERTS; e++) if (e != i1 && p[e] > p[i2]) i2 = e;
        float s2 = p[i1] + p[i2];
        g_pair_expert[warp * 2 + 0] = i1;
        g_pair_expert[warp * 2 + 1] = i2;
        g_pair_gate[warp * 2 + 0] = p[i1] / s2;
        g_pair_gate[warp * 2 + 1] = p[i2] / s2;
        g_pair_rank[warp * 2 + 0] = atomicAdd(&g_count[i1], 1);
        g_pair_rank[warp * 2 + 1] = atomicAdd(&g_count[i2], 1);
    }
}

// ---------------- offsets + tile->expert map (parallel) ----------------
__global__ void k_setup() {
    __shared__ int soff[N_EXPERTS + 1];
    if (threadIdx.x == 0) {
        int off = 0;
        for (int e = 0; e < N_EXPERTS; e++) {
            soff[e] = off; g_off[e] = off;
            off += (g_count[e] + BM - 1) / BM * BM;
        }
        soff[N_EXPERTS] = off; g_off[N_EXPERTS] = off;
    }
    __syncthreads();
    int i = threadIdx.x;
    if (i < MAX_TILES) {
        int r = i * BM, te = -1;
        if (r < soff[N_EXPERTS])
            for (int e = 0; e < N_EXPERTS; e++)
                if (r >= soff[e] && r < soff[e + 1]) { te = e; break; }
        g_tile_expert[i] = te;
    }
}

// ---------------- scatter ----------------
__global__ void k_scatter() {
    int i = blockIdx.x * blockDim.x + threadIdx.x;
    if (i >= NPAIRS) return;
    int e = g_pair_expert[i];
    int r = g_off[e] + g_pair_rank[i];
    g_sorted_token[r] = i >> 1;
    g_sorted_gate[r]  = g_pair_gate[i];
}

// ---------------- prepass: weights -> fp16; gather tokens -> fp16 --------
__global__ void k_prepw(const float* __restrict__ w1, const float* __restrict__ w2) {
    size_t n = (size_t)N_EXPERTS * D_FF * D_MODEL / 4;
    size_t stride = (size_t)gridDim.x * blockDim.x;
    for (size_t i = blockIdx.x * blockDim.x + threadIdx.x; i < n; i += stride) {
        float4 a = ((const float4*)w1)[i];
        ((__half2*)g_w1h)[i * 2 + 0] = __floats2half2_rn(a.x, a.y);
        ((__half2*)g_w1h)[i * 2 + 1] = __floats2half2_rn(a.z, a.w);
        float4 b = ((const float4*)w2)[i];
        ((__half2*)g_w2h)[i * 2 + 0] = __floats2half2_rn(b.x, b.y);
        ((__half2*)g_w2h)[i * 2 + 1] = __floats2half2_rn(b.z, b.w);
    }
}

__global__ void k_gather(const float* __restrict__ x) {
    int r = blockIdx.x;
    int t = g_sorted_token[r];
    int d = threadIdx.x * 4;
    float4 v = make_float4(0.f, 0.f, 0.f, 0.f);
    if (t >= 0) v = *(const float4*)&x[(size_t)t * D_MODEL + d];
    __half2* dst = (__half2*)&g_xh[(size_t)r * D_MODEL + d];
    dst[0] = __floats2half2_rn(v.x, v.y);
    dst[1] = __floats2half2_rn(v.z, v.w);
}

// ======================================================================
// fp16 GEMM: CTA 128x128, warps 2Mx4N (warp tile 64x32), m16n8k16,
// ldmatrix.x4 fragments, 3-stage cp.async ring (1 sync/chunk).
// G1: A=g_xh, B=g_w1h -> gelu -> g_Hh.   !G1: A=g_Hh, B=g_w2h -> out.
// ======================================================================
template<int KD, bool G1>
__global__ void __launch_bounds__(256, 2) k_gemm(const float* __restrict__ bias,
                                                 float* __restrict__ outp) {
    int e, r0, c0;
    if (G1) { e = g_tile_expert[blockIdx.x]; r0 = blockIdx.x * BM; c0 = blockIdx.y * BN; }
    else    { e = g_tile_expert[blockIdx.y]; r0 = blockIdx.y * BM; c0 = blockIdx.x * BN; }
    if (e < 0) return;

    extern __shared__ char sm[];
    int*   tok  = (int*)(sm + OFF_TOK);
    float* gate = (float*)(sm + OFF_GATE);

    int tid = threadIdx.x;
    if (tid < BM) {
        tok[tid]  = g_sorted_token[r0 + tid];
        gate[tid] = g_sorted_gate[r0 + tid];
    }
    __syncthreads();
    if (tok[0] < 0) return;

    int lane = tid & 31, wid = tid >> 5;
    int wm = (wid & 1) * 64;
    int wn = (wid >> 1) * 32;
    int g = lane >> 2, q = lane & 3;

    const __half* Ah = (G1 ? g_xh : g_Hh) + (size_t)r0 * KD;
    const __half* Bh = (G1 ? g_w1h : g_w2h) + ((size_t)e * (G1 ? D_FF : D_MODEL) + c0) * KD;

    // cp.async slots: 128 rows x 4 16B-chunks = 512 per matrix; 2 per thread
    int rowL0 = tid >> 2, cL = tid & 3;
    int rowL1 = rowL0 + 64;
    const __half* srcA0 = Ah + (size_t)rowL0 * KD + cL * 8;
    const __half* srcA1 = Ah + (size_t)rowL1 * KD + cL * 8;
    const __half* srcB0 = Bh + (size_t)rowL0 * KD + cL * 8;
    const __half* srcB1 = Bh + (size_t)rowL1 * KD + cL * 8;

    uint32_t sb = (uint32_t)__cvta_generic_to_shared(sm);
    uint32_t dA0 = sb + OFF_A + rowL0 * (SKW * 4) + cL * 16;
    uint32_t dA1 = sb + OFF_A + rowL1 * (SKW * 4) + cL * 16;
    uint32_t dB0 = sb + OFF_B + rowL0 * (SKW * 4) + cL * 16;
    uint32_t dB1 = sb + OFF_B + rowL1 * (SKW * 4) + cL * 16;

    // ldmatrix base addresses (per-lane)
    uint32_t aAddr[4], bAddr[2];
#pragma unroll
    for (int mi = 0; mi < 4; mi++) {
        int r = wm + mi * 16 + (lane & 7) + ((lane >> 3) & 1) * 8;
        int kof = ((lane >> 4) & 1) * 16;           // k+8 halfs = 16B
        aAddr[mi] = sb + OFF_A + r * (SKW * 4) + kof;
    }
#pragma unroll
    for (int pi = 0; pi < 2; pi++) {
        int r = wn + pi * 16 + (lane & 7) + ((lane >> 4) & 1) * 8;
        int kof = ((lane >> 3) & 1) * 16;
        bAddr[pi] = sb + OFF_B + r * (SKW * 4) + kof;
    }

    float acc[4][4][4] = {};
    const int NK = KD / KCH;

    // prologue: stages 0 and 1, separate groups
#pragma unroll
    for (int s = 0; s < 2; s++) {
        cp16(dA0 + s * MAT_STG, srcA0); cp16(dA1 + s * MAT_STG, srcA1);
        cp16(dB0 + s * MAT_STG, srcB0); cp16(dB1 + s * MAT_STG, srcB1);
        cp_commit();
        srcA0 += KCH; srcA1 += KCH; srcB0 += KCH; srcB1 += KCH;
    }
    cp_wait<1>();

    int s = 0;
    for (int k0 = 0; k0 < NK; k0++) {
        __syncthreads();
        uint32_t so = s * MAT_STG;
#pragma unroll
        for (int st = 0; st < 2; st++) {
            uint32_t ko = so + st * 32;
            unsigned a[4][4], b[2][4];
#pragma unroll
            for (int mi = 0; mi < 4; mi++) ldm_x4(a[mi], aAddr[mi] + ko);
#pragma unroll
            for (int pi = 0; pi < 2; pi++) ldm_x4(b[pi], bAddr[pi] + ko);
#pragma unroll
            for (int mi = 0; mi < 4; mi++)
#pragma unroll
                for (int ni = 0; ni < 4; ni++)
                    mma_f16(acc[mi][ni], a[mi], &b[ni >> 1][(ni & 1) * 2]);
        }
        // load stage s (just freed -> becomes k0+2's data 3 iters ahead mod 3)
        if (k0 + 2 < NK) {
            uint32_t wo = s * MAT_STG;   // (k0+2) % 3 == s is wrong; compute target
            int tgt = (k0 + 2) % NSTG;
            wo = tgt * MAT_STG;
            cp16(dA0 + wo, srcA0); cp16(dA1 + wo, srcA1);
            cp16(dB0 + wo, srcB0); cp16(dB1 + wo, srcB1);
            srcA0 += KCH; srcA1 += KCH; srcB0 += KCH; srcB1 += KCH;
        }
        cp_commit();
        cp_wait<1>();
        s = (s + 1 == NSTG) ? 0 : s + 1;
    }

    // epilogue
#pragma unroll
    for (int mi = 0; mi < 4; mi++) {
#pragma unroll
        for (int half = 0; half < 2; half++) {
            int row = wm + mi * 16 + g + half * 8;
            int t = tok[row];
            if (t < 0) continue;
            float gw = gate[row];
#pragma unroll
            for (int ni = 0; ni < 4; ni++) {
                int col = c0 + wn + ni * 8 + q * 2;
                if (G1) {
                    float v0 = acc[mi][ni][half * 2 + 0] + bias[e * D_FF + col];
                    float v1 = acc[mi][ni][half * 2 + 1] + bias[e * D_FF + col + 1];
                    v0 = 0.5f * v0 * (1.0f + erff(v0 * 0.70710678118654752f));
                    v1 = 0.5f * v1 * (1.0f + erff(v1 * 0.70710678118654752f));
                    *(__half2*)&g_Hh[(size_t)(r0 + row) * D_FF + col] =
                        __floats2half2_rn(v0, v1);
                } else {
                    float v0 = gw * (acc[mi][ni][half * 2 + 0] + bias[e * D_MODEL + col]);
                    float v1 = gw * (acc[mi][ni][half * 2 + 1] + bias[e * D_MODEL + col + 1]);
                    atomicAdd(&outp[(size_t)t * D_MODEL + col], v0);
                    atomicAdd(&outp[(size_t)t * D_MODEL + col + 1], v1);
                }
            }
        }
    }
}

// ---------------- launch ----------------
extern "C" void kernel_launch(void* const* d_in, const int* in_sizes, int n_in,
                              void* d_out, int out_size) {
    (void)in_sizes; (void)n_in; (void)out_size;
    const float* x  = (const float*)d_in[0];
    const float* rw = (const float*)d_in[1];
    const float* rb = (const float*)d_in[2];
    const float* w1 = (const float*)d_in[3];
    const float* b1 = (const float*)d_in[4];
    const float* w2 = (const float*)d_in[5];
    const float* b2 = (const float*)d_in[6];
    float* out = (float*)d_out;

    cudaFuncSetAttribute(k_gemm<D_MODEL, true>,
                         cudaFuncAttributeMaxDynamicSharedMemorySize, SMEM_SZ);
    cudaFuncSetAttribute(k_gemm<D_FF, false>,
                         cudaFuncAttributeMaxDynamicSharedMemorySize, SMEM_SZ);

    k_init<<<1024, 256>>>(out);
    k_prepw<<<2048, 256>>>(w1, w2);
    k_router<<<T_TOKENS / 8, 256>>>(x, rw, rb);
    k_setup<<<1, 256>>>();
    k_scatter<<<(NPAIRS + 255) / 256, 256>>>();
    k_gather<<<ROWS_CAP, 256>>>(x);
    k_gemm<D_MODEL, true><<<dim3(MAX_TILES, D_FF / BN), 256, SMEM_SZ>>>(b1, (float*)0);
    k_gemm<D_FF, false><<<dim3(D_MODEL / BN, MAX_TILES), 256, SMEM_SZ>>>(b2, out);
}